// round 13
// baseline (speedup 1.0000x reference)
#include <cuda_runtime.h>

// WaveletSparsityLoss: 3-level Haar DWT sparsity loss on [32,1,1024,1024] fp32.
// Paired-thread streaming (R12, best streaming phase: dense 16B-strided warp
// loads). Grid reduction via fire-and-forget RED.ADD.F32 into a self-cleaning
// __device__ accumulator: the last-ticket block copies it to d_out[0] and
// resets state for the next graph replay. This removes the cudaMemsetAsync
// graph node, which measured ~2.5-2.9us of wall time per replay.

#define IMG          1024
#define TILES_X      128                    // 1024/8
#define TILES_PER_IMG (TILES_X * TILES_X)   // 16384
#define BATCH        32
#define TOTAL_TILES  (BATCH * TILES_PER_IMG)// 524288
#define TPB          256
#define NBLOCKS      (2 * TOTAL_TILES / TPB) // 4096 (2 threads per tile)

__device__ float        g_acc    = 0.0f;    // reset by last block each launch
__device__ unsigned int g_ticket = 0;       // reset by last block each launch

// Thresholds (NORMALIZE=True): thr_s = (50 / 2^(level_idx-1)) / 255
// Per-coefficient scale: weight_s / (3 * N_s)
#define THR1 (50.0f / (4.0f * 255.0f))
#define THR2 (50.0f / (2.0f * 255.0f))
#define THR3 (50.0f / 255.0f)
#define C1   (1.0f / (3.0f * 3.0f * 8388608.0f))
#define C2   (1.0f / (2.0f * 3.0f * 2097152.0f))
#define C3   (1.0f / (1.0f * 3.0f * 524288.0f))

__device__ __forceinline__ float band3(float a, float b, float c, float d, float thr,
                                       float* cA) {
    float s0 = a + b, s1 = c + d;
    float d0 = a - b, d1 = c - d;
    float cH = (s0 - s1) * 0.5f;
    float cV = (d0 + d1) * 0.5f;
    float cD = (d0 - d1) * 0.5f;
    *cA = (s0 + s1) * 0.5f;
    return fminf(fabsf(cH), thr) + fminf(fabsf(cV), thr) + fminf(fabsf(cD), thr);
}

__global__ void __launch_bounds__(TPB)
wavelet_tiles_kernel(const float* __restrict__ pred, float* __restrict__ out) {
    const int gtid = blockIdx.x * TPB + threadIdx.x;
    const int tile = gtid >> 1;               // tile id (2 threads per tile)
    const int half = gtid & 1;                // 0 = cols 0-3, 1 = cols 4-7

    const int b  = tile / TILES_PER_IMG;
    const int t  = tile - b * TILES_PER_IMG;
    const int ty = t / TILES_X;
    const int tx = t - ty * TILES_X;

    const float* base = pred + (size_t)b * (IMG * IMG)
                             + (size_t)ty * 8 * IMG + (size_t)tx * 8 + half * 4;

    // 8 rows x 4 cols: one dense float4 per row. Warp-wide: lane addresses
    // are 16B-strided -> each LDG.128 covers a contiguous 512B span.
    float x[8][4];
    #pragma unroll
    for (int row = 0; row < 8; ++row) {
        const float4 v = __ldg((const float4*)(base + (size_t)row * IMG));
        x[row][0] = v.x; x[row][1] = v.y; x[row][2] = v.z; x[row][3] = v.w;
    }

    // Level 1: 8x4 half-tile -> 4x2 cA block (8 of the tile's 16 quads).
    float A1[4][2];
    float s1 = 0.0f;
    #pragma unroll
    for (int i = 0; i < 4; ++i) {
        #pragma unroll
        for (int j = 0; j < 2; ++j) {
            s1 += band3(x[2*i][2*j], x[2*i][2*j+1], x[2*i+1][2*j], x[2*i+1][2*j+1],
                        THR1, &A1[i][j]);
        }
    }

    // Level 2: thread-local quad (this thread's A1 columns are the tile's
    // global columns {2*half, 2*half+1}).
    float A2loc[2];   // = global A2[i2][half]
    float s2 = 0.0f;
    #pragma unroll
    for (int i = 0; i < 2; ++i) {
        s2 += band3(A1[2*i][0], A1[2*i][1], A1[2*i+1][0], A1[2*i+1][1],
                    THR2, &A2loc[i]);
    }

    // Level 3: exchange the pair's A2 column via shfl. band3's loss terms are
    // invariant under (a<->b, c<->d) swap, so both threads compute the same
    // s3 and each contributes half.
    const float p0 = __shfl_xor_sync(0xffffffffu, A2loc[0], 1);
    const float p1 = __shfl_xor_sync(0xffffffffu, A2loc[1], 1);
    float cA3;
    const float s3 = band3(A2loc[0], p0, A2loc[1], p1, THR3, &cA3);

    float val = s1 * C1 + s2 * C2 + s3 * (0.5f * C3);

    // Warp tree reduce (fixed order, deterministic within block).
    #pragma unroll
    for (int off = 16; off > 0; off >>= 1)
        val += __shfl_xor_sync(0xffffffffu, val, off);

    __shared__ float warp_sums[TPB / 32];
    const int lane = threadIdx.x & 31;
    const int wid  = threadIdx.x >> 5;
    if (lane == 0) warp_sums[wid] = val;
    __syncthreads();          // the only block-wide barrier

    // Warps 1..7 retire here. Thread 0: fire-and-forget RED into g_acc,
    // release-ticket; the last block publishes and resets state.
    if (threadIdx.x == 0) {
        float s = 0.0f;
        #pragma unroll
        for (int w = 0; w < TPB / 32; ++w) s += warp_sums[w];

        atomicAdd(&g_acc, s);   // result unused -> RED.ADD.F32, no wait

        unsigned int ticket;
        // Release: orders the RED above before the ticket; the winning
        // block's acquire (below, via ld.acquire) then sees all REDs.
        asm volatile("atom.acq_rel.gpu.global.add.u32 %0, [%1], %2;"
                     : "=r"(ticket)
                     : "l"(&g_ticket), "r"(1u)
                     : "memory");

        if (ticket == NBLOCKS - 1) {
            float total;
            asm volatile("ld.acquire.gpu.global.f32 %0, [%1];"
                         : "=f"(total)
                         : "l"(&g_acc)
                         : "memory");
            out[0] = total;
            // Reset for the next graph replay (kernel completion boundary
            // orders these stores before the next launch's accesses).
            g_acc    = 0.0f;
            g_ticket = 0;
        }
    }
}

extern "C" void kernel_launch(void* const* d_in, const int* in_sizes, int n_in,
                              void* d_out, int out_size) {
    const float* pred = (const float*)d_in[0];
    float* out = (float*)d_out;
    wavelet_tiles_kernel<<<NBLOCKS, TPB>>>(pred, out);
}